// round 3
// baseline (speedup 1.0000x reference)
#include <cuda_runtime.h>

#define NQ_MAX 50000
#define NC 128
#define NG 8
#define NS 16

typedef unsigned long long u64;

__device__ float g_q[NQ_MAX * NC];
__device__ float g_k[NQ_MAX * NC];
__device__ float g_v[NQ_MAX * NC];

__device__ __forceinline__ u64 fma2(u64 a, u64 b, u64 c) {
    u64 d;
    asm("fma.rn.f32x2 %0, %1, %2, %3;" : "=l"(d) : "l"(a), "l"(b), "l"(c));
    return d;
}
__device__ __forceinline__ u64 mul2(u64 a, u64 b) {
    u64 d;
    asm("mul.rn.f32x2 %0, %1, %2;" : "=l"(d) : "l"(a), "l"(b));
    return d;
}
__device__ __forceinline__ u64 add2(u64 a, u64 b) {
    u64 d;
    asm("add.rn.f32x2 %0, %1, %2;" : "=l"(d) : "l"(a), "l"(b));
    return d;
}
__device__ __forceinline__ u64 splat2(float x) {
    u64 d;
    asm("mov.b64 %0, {%1, %2};" : "=l"(d) : "f"(x), "f"(x));
    return d;
}
__device__ __forceinline__ void unpack2(u64 d, float& lo, float& hi) {
    asm("mov.b64 {%0, %1}, %2;" : "=f"(lo), "=f"(hi) : "l"(d));
}

// ---------------------------------------------------------------------------
// Projection GEMM with packed f32x2 FMAs.
// Y[m,c] = sum_k X[m,k] * W[c,k] + b[c].  BM=128, BN=128, BK=16.
// 256 threads, 8x8 per-thread tile; accumulators are 32 f32x2 pairs.
// ---------------------------------------------------------------------------
__global__ void __launch_bounds__(256) proj_kernel(
    const float* __restrict__ x, const float* __restrict__ x2,
    const float* __restrict__ Wq, const float* __restrict__ bq,
    const float* __restrict__ Wk, const float* __restrict__ bk,
    const float* __restrict__ Wv, const float* __restrict__ bv,
    int n, int n2)
{
    const float *X, *W, *bias;
    float* Y;
    int M;
    if (blockIdx.y == 0)      { X = x;  W = Wq; bias = bq; Y = g_q; M = n;  }
    else if (blockIdx.y == 1) { X = x2; W = Wk; bias = bk; Y = g_k; M = n2; }
    else                      { X = x2; W = Wv; bias = bv; Y = g_v; M = n2; }

    __shared__ float As[16][128];   // [k][m]
    __shared__ float Bs[16][128];   // [k][c]

    const int t = threadIdx.x;
    const int block_m = blockIdx.x * 128;
    if (block_m >= M) return;

    const int tm = (t >> 4) << 3;
    const int tn = (t & 15) << 3;

    u64 acc2[8][4];
#pragma unroll
    for (int i = 0; i < 8; i++)
#pragma unroll
        for (int j = 0; j < 4; j++) acc2[i][j] = 0ull;

    for (int k0 = 0; k0 < 128; k0 += 16) {
#pragma unroll
        for (int it = 0; it < 2; it++) {
            int r  = (it << 6) + (t >> 2);
            int kc = (t & 3) << 2;
            int gr = block_m + r;
            float4 xv = make_float4(0.f, 0.f, 0.f, 0.f);
            if (gr < M) xv = *(const float4*)(X + (size_t)gr * 128 + k0 + kc);
            As[kc + 0][r] = xv.x; As[kc + 1][r] = xv.y;
            As[kc + 2][r] = xv.z; As[kc + 3][r] = xv.w;
            float4 wv = *(const float4*)(W + (size_t)r * 128 + k0 + kc);
            Bs[kc + 0][r] = wv.x; Bs[kc + 1][r] = wv.y;
            Bs[kc + 2][r] = wv.z; Bs[kc + 3][r] = wv.w;
        }
        __syncthreads();
#pragma unroll
        for (int k = 0; k < 16; k++) {
            float a[8];
            *(float4*)&a[0] = *(const float4*)&As[k][tm];
            *(float4*)&a[4] = *(const float4*)&As[k][tm + 4];
            u64 b2[4];
            {
                const ulonglong2* bp = (const ulonglong2*)&Bs[k][tn];
                ulonglong2 v0 = bp[0], v1 = bp[1];
                b2[0] = v0.x; b2[1] = v0.y; b2[2] = v1.x; b2[3] = v1.y;
            }
#pragma unroll
            for (int i = 0; i < 8; i++) {
                const u64 a2 = splat2(a[i]);
#pragma unroll
                for (int j = 0; j < 4; j++)
                    acc2[i][j] = fma2(a2, b2[j], acc2[i][j]);
            }
        }
        __syncthreads();
    }

    float bl[8];
#pragma unroll
    for (int j = 0; j < 8; j++) bl[j] = bias[tn + j];

#pragma unroll
    for (int i = 0; i < 8; i++) {
        int gr = block_m + tm + i;
        if (gr < M) {
            float o[8];
#pragma unroll
            for (int j = 0; j < 4; j++) {
                float lo, hi;
                unpack2(acc2[i][j], lo, hi);
                o[2 * j]     = lo + bl[2 * j];
                o[2 * j + 1] = hi + bl[2 * j + 1];
            }
            *(float4*)(Y + (size_t)gr * 128 + tn)     = *(float4*)&o[0];
            *(float4*)(Y + (size_t)gr * 128 + tn + 4) = *(float4*)&o[4];
        }
    }
}

// ---------------------------------------------------------------------------
// Fused gather + positional MLP + grouped attention.
// One warp per query, lane l -> channels [4l,4l+4), group g = l>>2.
// logits: sum_c (k_c+prk)(q_c+prq) = k.q + prk*Sq + prq*Sk + 16*prk*prq
// Fold u = kq_part + prq*ks_part before the 4-lane butterfly (2 shfls not 4).
// ---------------------------------------------------------------------------
__global__ void __launch_bounds__(256) attn_kernel(
    const float* __restrict__ p, const float* __restrict__ p2,
    const int* __restrict__ idx,
    const float* __restrict__ W1, const float* __restrict__ b1,
    const float* __restrict__ bng, const float* __restrict__ bnb,
    const float* __restrict__ bnm, const float* __restrict__ bnv,
    const float* __restrict__ W2, const float* __restrict__ b2,
    float* __restrict__ out, int n)
{
    __shared__ float sA[9];
    __shared__ float sc[3];
    __shared__ float sW2[16][3];
    __shared__ float sb2[16];

    const int t = threadIdx.x;
    if (t < 9) {
        int r = t / 3;
        float s = bng[r] * rsqrtf(bnv[r] + 1e-5f);
        sA[t] = s * W1[t];
    }
    if (t < 3) sc[t] = bng[t] * rsqrtf(bnv[t] + 1e-5f) * (b1[t] - bnm[t]) + bnb[t];
    if (t < 48) sW2[t / 3][t % 3] = W2[t];
    if (t < 16) sb2[t] = b2[t];
    __syncthreads();

    const int warp = t >> 5;
    const int lane = t & 31;
    const int i = blockIdx.x * 8 + warp;
    if (i >= n) return;

    const int g = lane >> 2;
    const float w2q0 = sW2[g][0], w2q1 = sW2[g][1], w2q2 = sW2[g][2], b2q = sb2[g];
    const float w2k0 = sW2[8 + g][0], w2k1 = sW2[8 + g][1], w2k2 = sW2[8 + g][2], b2k = sb2[8 + g];

    const ulonglong2 qv = *(const ulonglong2*)(g_q + (size_t)i * 128 + lane * 4);
    const u64 q01 = qv.x, q23 = qv.y;
    float qs;
    {
        float lo, hi;
        unpack2(add2(q01, q23), lo, hi);
        qs = lo + hi;
        qs += __shfl_xor_sync(0xffffffffu, qs, 1);
        qs += __shfl_xor_sync(0xffffffffu, qs, 2);
    }

    const float px = p[i * 3 + 0], py = p[i * 3 + 1], pz = p[i * 3 + 2];

    int nb[16];
    {
        const int4* ip = (const int4*)(idx + (size_t)i * 16);
#pragma unroll
        for (int s4 = 0; s4 < 4; s4++) {
            int4 v = ip[s4];
            nb[s4 * 4 + 0] = v.x; nb[s4 * 4 + 1] = v.y;
            nb[s4 * 4 + 2] = v.z; nb[s4 * 4 + 3] = v.w;
        }
    }

    float logit[16];
#pragma unroll
    for (int s = 0; s < 16; s++) {
        const int j = nb[s];
        const ulonglong2 kv = *(const ulonglong2*)(g_k + (size_t)j * 128 + lane * 4);

        u64 t2 = mul2(kv.x, q01);
        t2 = fma2(kv.y, q23, t2);
        const u64 s2 = add2(kv.x, kv.y);

        float kqlo, kqhi, kslo, kshi;
        unpack2(t2, kqlo, kqhi);
        unpack2(s2, kslo, kshi);
        const float kq = kqlo + kqhi;
        const float ksp = kslo + kshi;

        const float rx = p2[j * 3 + 0] - px;
        const float ry = p2[j * 3 + 1] - py;
        const float rz = p2[j * 3 + 2] - pz;
        const float h0 = fmaxf(sA[0] * rx + sA[1] * ry + sA[2] * rz + sc[0], 0.f);
        const float h1 = fmaxf(sA[3] * rx + sA[4] * ry + sA[5] * rz + sc[1], 0.f);
        const float h2 = fmaxf(sA[6] * rx + sA[7] * ry + sA[8] * rz + sc[2], 0.f);
        const float prq = w2q0 * h0 + w2q1 * h1 + w2q2 * h2 + b2q;
        const float prk = w2k0 * h0 + w2k1 * h1 + w2k2 * h2 + b2k;

        float u = fmaf(prq, ksp, kq);
        u += __shfl_xor_sync(0xffffffffu, u, 1);
        u += __shfl_xor_sync(0xffffffffu, u, 2);

        logit[s] = 0.25f * (u + prk * (qs + 16.f * prq));
    }

    float mx = logit[0];
#pragma unroll
    for (int s = 1; s < 16; s++) mx = fmaxf(mx, logit[s]);
    float denom = 0.f;
#pragma unroll
    for (int s = 0; s < 16; s++) {
        logit[s] = __expf(logit[s] - mx);
        denom += logit[s];
    }
    const float inv = 1.f / denom;

    u64 o01 = 0ull, o23 = 0ull;
#pragma unroll
    for (int s = 0; s < 16; s++) {
        const float w = logit[s] * inv;
        const u64 w2 = splat2(w);
        const ulonglong2 vv = *(const ulonglong2*)(g_v + (size_t)nb[s] * 128 + lane * 4);
        o01 = fma2(w2, vv.x, o01);
        o23 = fma2(w2, vv.y, o23);
    }
    ulonglong2 ov; ov.x = o01; ov.y = o23;
    *(ulonglong2*)(out + (size_t)i * 128 + lane * 4) = ov;
}

extern "C" void kernel_launch(void* const* d_in, const int* in_sizes, int n_in,
                              void* d_out, int out_size)
{
    const float* p   = (const float*)d_in[0];
    const float* x   = (const float*)d_in[1];
    const float* p2  = (const float*)d_in[2];
    const float* x2  = (const float*)d_in[3];
    const int*   idx = (const int*)d_in[4];
    const float* Wq  = (const float*)d_in[5];
    const float* bq  = (const float*)d_in[6];
    const float* Wk  = (const float*)d_in[7];
    const float* bk  = (const float*)d_in[8];
    const float* Wv  = (const float*)d_in[9];
    const float* bv  = (const float*)d_in[10];
    const float* W1  = (const float*)d_in[11];
    const float* b1  = (const float*)d_in[12];
    const float* bng = (const float*)d_in[13];
    const float* bnb = (const float*)d_in[14];
    const float* bnm = (const float*)d_in[15];
    const float* bnv = (const float*)d_in[16];
    const float* W2  = (const float*)d_in[17];
    const float* b2  = (const float*)d_in[18];
    float* out = (float*)d_out;

    const int n  = in_sizes[1] / NC;
    const int n2 = in_sizes[3] / NC;
    const int mmax = n > n2 ? n : n2;

    dim3 pg((mmax + 127) / 128, 3);
    proj_kernel<<<pg, 256>>>(x, x2, Wq, bq, Wk, bk, Wv, bv, n, n2);
    attn_kernel<<<(n + 7) / 8, 256>>>(p, p2, idx, W1, b1, bng, bnb, bnm, bnv,
                                      W2, b2, out, n);
}

// round 4
// speedup vs baseline: 1.3360x; 1.3360x over previous
#include <cuda_runtime.h>
#include <mma.h>

using namespace nvcuda;

#define NQ_MAX 50000
#define NC 128
#define NG 8
#define NS 16

// Padded by 128 rows: partial-tile wmma stores at the M edge write zeros into
// the pad instead of the neighboring buffer.
__device__ float g_q[(NQ_MAX + 128) * NC];
__device__ float g_k[(NQ_MAX + 128) * NC];
__device__ float g_v[(NQ_MAX + 128) * NC];

__device__ __forceinline__ float to_tf32(float x) {
    float r;
    asm("cvt.rna.tf32.f32 %0, %1;" : "=f"(r) : "f"(x));
    return r;
}

// ---------------------------------------------------------------------------
// Projection GEMM (tf32 tensor cores): Y[m,c] = sum_k X[m,k] * W[c,k]
// (NO bias — all biases folded into the attention kernel algebraically.)
// Block tile 128x128, BK=32 staged in smem, 8 warps: 4(M) x 2(N),
// warp tile 32x64 = 2x4 wmma m16n16k8 fragments.
// ---------------------------------------------------------------------------
#define LDA 36

__global__ void __launch_bounds__(256) proj_kernel(
    const float* __restrict__ x, const float* __restrict__ x2,
    const float* __restrict__ Wq, const float* __restrict__ Wk,
    const float* __restrict__ Wv,
    int n, int n2)
{
    const float *X, *W;
    float* Y;
    int M;
    if (blockIdx.y == 0)      { X = x;  W = Wq; Y = g_q; M = n;  }
    else if (blockIdx.y == 1) { X = x2; W = Wk; Y = g_k; M = n2; }
    else                      { X = x2; W = Wv; Y = g_v; M = n2; }

    __shared__ float As[128 * LDA];   // A[m][k] row-major, ld=LDA
    __shared__ float Bs[128 * LDA];   // Bs[c*LDA+k] = W[c][k]  (B col-major k x c)

    const int t = threadIdx.x;
    const int block_m = blockIdx.x * 128;
    if (block_m >= M) return;

    const int warp = t >> 5;
    const int wm = (warp & 3) * 32;
    const int wn = (warp >> 2) * 64;

    wmma::fragment<wmma::accumulator, 16, 16, 8, float> acc[2][4];
#pragma unroll
    for (int i = 0; i < 2; i++)
#pragma unroll
        for (int j = 0; j < 4; j++) wmma::fill_fragment(acc[i][j], 0.0f);

    for (int k0 = 0; k0 < 128; k0 += 32) {
        // Stage A (128x32) and B (128x32), converting to tf32 bits.
#pragma unroll
        for (int it = 0; it < 4; it++) {
            int lin = it * 256 + t;
            int r = lin >> 3;
            int c4 = (lin & 7) << 2;
            int gr = block_m + r;
            float4 xv = make_float4(0.f, 0.f, 0.f, 0.f);
            if (gr < M) xv = *(const float4*)(X + (size_t)gr * 128 + k0 + c4);
            As[r * LDA + c4 + 0] = to_tf32(xv.x);
            As[r * LDA + c4 + 1] = to_tf32(xv.y);
            As[r * LDA + c4 + 2] = to_tf32(xv.z);
            As[r * LDA + c4 + 3] = to_tf32(xv.w);
            float4 wv = *(const float4*)(W + (size_t)r * 128 + k0 + c4);
            Bs[r * LDA + c4 + 0] = to_tf32(wv.x);
            Bs[r * LDA + c4 + 1] = to_tf32(wv.y);
            Bs[r * LDA + c4 + 2] = to_tf32(wv.z);
            Bs[r * LDA + c4 + 3] = to_tf32(wv.w);
        }
        __syncthreads();

#pragma unroll
        for (int kk = 0; kk < 32; kk += 8) {
            wmma::fragment<wmma::matrix_a, 16, 16, 8, wmma::precision::tf32, wmma::row_major> a[2];
            wmma::fragment<wmma::matrix_b, 16, 16, 8, wmma::precision::tf32, wmma::col_major> b[4];
#pragma unroll
            for (int i = 0; i < 2; i++)
                wmma::load_matrix_sync(a[i], As + (wm + i * 16) * LDA + kk, LDA);
#pragma unroll
            for (int j = 0; j < 4; j++)
                wmma::load_matrix_sync(b[j], Bs + (wn + j * 16) * LDA + kk, LDA);
#pragma unroll
            for (int i = 0; i < 2; i++)
#pragma unroll
                for (int j = 0; j < 4; j++)
                    wmma::mma_sync(acc[i][j], a[i], b[j], acc[i][j]);
        }
        __syncthreads();
    }

#pragma unroll
    for (int i = 0; i < 2; i++)
#pragma unroll
        for (int j = 0; j < 4; j++)
            wmma::store_matrix_sync(
                Y + (size_t)(block_m + wm + i * 16) * 128 + wn + j * 16,
                acc[i][j], 128, wmma::mem_row_major);
}

// ---------------------------------------------------------------------------
// Fused gather + positional MLP + grouped attention (bias-folded).
// One warp per query. Lane l -> channels [4l,4l+4), group g = l>>2.
// logit = 0.25*(u + beta + prq*Bg + prk*(Sq + 16*prq)) where
//   u (butterflied) = sum k_raw*q' + prq * sum k_raw,
//   beta = sum bk*q',  Bg = sum_{c in g} bk_c,  Sq = sum q' (group).
// out = sum_s w_s * v_raw + bv  (softmax weights sum to 1).
// ---------------------------------------------------------------------------
__global__ void __launch_bounds__(256) attn_kernel(
    const float* __restrict__ p, const float* __restrict__ p2,
    const int* __restrict__ idx,
    const float* __restrict__ bq, const float* __restrict__ bk,
    const float* __restrict__ bv,
    const float* __restrict__ W1, const float* __restrict__ b1,
    const float* __restrict__ bng, const float* __restrict__ bnb,
    const float* __restrict__ bnm, const float* __restrict__ bnv,
    const float* __restrict__ W2, const float* __restrict__ b2,
    float* __restrict__ out, int n)
{
    __shared__ float sA[9];
    __shared__ float sc[3];
    __shared__ float sW2[16][3];
    __shared__ float sb2[16];
    __shared__ float sBg[8];

    const int t = threadIdx.x;
    if (t < 9) {
        int r = t / 3;
        float s = bng[r] * rsqrtf(bnv[r] + 1e-5f);
        sA[t] = s * W1[t];
    }
    if (t < 3) sc[t] = bng[t] * rsqrtf(bnv[t] + 1e-5f) * (b1[t] - bnm[t]) + bnb[t];
    if (t < 48) sW2[t / 3][t % 3] = W2[t];
    if (t < 16) sb2[t] = b2[t];
    if (t < 8) {
        float s = 0.f;
#pragma unroll
        for (int c = 0; c < 16; c++) s += bk[t * 16 + c];
        sBg[t] = s;
    }
    __syncthreads();

    const int warp = t >> 5;
    const int lane = t & 31;
    const int i = blockIdx.x * 8 + warp;
    if (i >= n) return;

    const int g = lane >> 2;
    const float w2q0 = sW2[g][0], w2q1 = sW2[g][1], w2q2 = sW2[g][2], b2q = sb2[g];
    const float w2k0 = sW2[8 + g][0], w2k1 = sW2[8 + g][1], w2k2 = sW2[8 + g][2], b2k = sb2[8 + g];
    const float Bg = sBg[g];

    // q' = q_raw + bq
    float4 q4 = *(const float4*)(g_q + (size_t)i * 128 + lane * 4);
    const float4 bq4 = *(const float4*)(bq + lane * 4);
    q4.x += bq4.x; q4.y += bq4.y; q4.z += bq4.z; q4.w += bq4.w;

    const float4 bk4 = *(const float4*)(bk + lane * 4);

    float qs = q4.x + q4.y + q4.z + q4.w;
    float beta = bk4.x * q4.x + bk4.y * q4.y + bk4.z * q4.z + bk4.w * q4.w;
    qs   += __shfl_xor_sync(0xffffffffu, qs, 1);
    beta += __shfl_xor_sync(0xffffffffu, beta, 1);
    qs   += __shfl_xor_sync(0xffffffffu, qs, 2);
    beta += __shfl_xor_sync(0xffffffffu, beta, 2);

    const float px = p[i * 3 + 0], py = p[i * 3 + 1], pz = p[i * 3 + 2];

    int nb[16];
    {
        const int4* ip = (const int4*)(idx + (size_t)i * 16);
#pragma unroll
        for (int s4 = 0; s4 < 4; s4++) {
            int4 v = ip[s4];
            nb[s4 * 4 + 0] = v.x; nb[s4 * 4 + 1] = v.y;
            nb[s4 * 4 + 2] = v.z; nb[s4 * 4 + 3] = v.w;
        }
    }

    float logit[16];
#pragma unroll
    for (int s = 0; s < 16; s++) {
        const int j = nb[s];
        const float4 k4 = *(const float4*)(g_k + (size_t)j * 128 + lane * 4);
        float kq = k4.x * q4.x + k4.y * q4.y + k4.z * q4.z + k4.w * q4.w;
        float ks = k4.x + k4.y + k4.z + k4.w;

        const float rx = p2[j * 3 + 0] - px;
        const float ry = p2[j * 3 + 1] - py;
        const float rz = p2[j * 3 + 2] - pz;
        const float h0 = fmaxf(sA[0] * rx + sA[1] * ry + sA[2] * rz + sc[0], 0.f);
        const float h1 = fmaxf(sA[3] * rx + sA[4] * ry + sA[5] * rz + sc[1], 0.f);
        const float h2 = fmaxf(sA[6] * rx + sA[7] * ry + sA[8] * rz + sc[2], 0.f);
        const float prq = w2q0 * h0 + w2q1 * h1 + w2q2 * h2 + b2q;
        const float prk = w2k0 * h0 + w2k1 * h1 + w2k2 * h2 + b2k;

        float u = fmaf(prq, ks, kq);
        u += __shfl_xor_sync(0xffffffffu, u, 1);
        u += __shfl_xor_sync(0xffffffffu, u, 2);

        logit[s] = 0.25f * (u + beta + prq * Bg + prk * fmaf(16.f, prq, qs));
    }

    float mx = logit[0];
#pragma unroll
    for (int s = 1; s < 16; s++) mx = fmaxf(mx, logit[s]);
    float denom = 0.f;
#pragma unroll
    for (int s = 0; s < 16; s++) {
        logit[s] = __expf(logit[s] - mx);
        denom += logit[s];
    }
    const float inv = 1.f / denom;

    float4 o = make_float4(0.f, 0.f, 0.f, 0.f);
#pragma unroll
    for (int s = 0; s < 16; s++) {
        const float w = logit[s] * inv;
        const float4 v4 = *(const float4*)(g_v + (size_t)nb[s] * 128 + lane * 4);
        o.x = fmaf(w, v4.x, o.x);
        o.y = fmaf(w, v4.y, o.y);
        o.z = fmaf(w, v4.z, o.z);
        o.w = fmaf(w, v4.w, o.w);
    }
    const float4 bv4 = *(const float4*)(bv + lane * 4);
    o.x += bv4.x; o.y += bv4.y; o.z += bv4.z; o.w += bv4.w;
    *(float4*)(out + (size_t)i * 128 + lane * 4) = o;
}

extern "C" void kernel_launch(void* const* d_in, const int* in_sizes, int n_in,
                              void* d_out, int out_size)
{
    const float* p   = (const float*)d_in[0];
    const float* x   = (const float*)d_in[1];
    const float* p2  = (const float*)d_in[2];
    const float* x2  = (const float*)d_in[3];
    const int*   idx = (const int*)d_in[4];
    const float* Wq  = (const float*)d_in[5];
    const float* bq  = (const float*)d_in[6];
    const float* Wk  = (const float*)d_in[7];
    const float* bk  = (const float*)d_in[8];
    const float* Wv  = (const float*)d_in[9];
    const float* bv  = (const float*)d_in[10];
    const float* W1  = (const float*)d_in[11];
    const float* b1  = (const float*)d_in[12];
    const float* bng = (const float*)d_in[13];
    const float* bnb = (const float*)d_in[14];
    const float* bnm = (const float*)d_in[15];
    const float* bnv = (const float*)d_in[16];
    const float* W2  = (const float*)d_in[17];
    const float* b2  = (const float*)d_in[18];
    float* out = (float*)d_out;

    const int n  = in_sizes[1] / NC;
    const int n2 = in_sizes[3] / NC;
    const int mmax = n > n2 ? n : n2;

    dim3 pg((mmax + 127) / 128, 3);
    proj_kernel<<<pg, 256>>>(x, x2, Wq, Wk, Wv, n, n2);
    attn_kernel<<<(n + 7) / 8, 256>>>(p, p2, idx, bq, bk, bv,
                                      W1, b1, bng, bnb, bnm, bnv,
                                      W2, b2, out, n);
}